// round 1
// baseline (speedup 1.0000x reference)
#include <cuda_runtime.h>
#include <math.h>

#define DHEAD 128
#define BM 64
#define BN 64
#define NTHREADS 256
#define PS_STRIDE 68   // 64 + 4 pad, keeps rows 16B-aligned, reduces STS conflicts

// Flash-attention, fp32, register-blocked.
// Grid: (Q/BM, B). Block: 256 threads as 16x16 (tx = key-col group, ty = q-row group).
// Thread computes S micro-tile [4q x 4k] and O micro-tile [4q x 8d]
// (d columns split as {4*tx..4*tx+3} and {64+4*tx..67+4*tx} to avoid smem bank conflicts).
__global__ __launch_bounds__(NTHREADS)
void attn_fp32_kernel(const float* __restrict__ qg,
                      const float* __restrict__ kg,
                      const float* __restrict__ vg,
                      const int*   __restrict__ vlen,
                      float*       __restrict__ outg,
                      int Qlen, int Klen)
{
    const int b  = blockIdx.y;
    const int q0 = blockIdx.x * BM;

    extern __shared__ float smem[];
    float* Qs = smem;                      // [DHEAD][BM]  transposed, 32KB
    float* Ks = Qs + DHEAD * BM;           // [DHEAD][BN]  transposed, 32KB
    float* Vs = Ks + DHEAD * BN;           // [BN][DHEAD]  row-major,  32KB
    float* Ps = Vs + BN * DHEAD;           // [BN][PS_STRIDE] (P transposed: [k][q]), 17KB

    const int tid = threadIdx.x;
    const int tx = tid & 15;               // key-col group
    const int ty = tid >> 4;               // q-row group
    const float scale = rsqrtf((float)DHEAD);

    // ---- Load Q tile transposed (and pre-scaled) ----
    const float* qb = qg + ((long)b * Qlen + q0) * DHEAD;
    for (int i = tid; i < BM * (DHEAD / 4); i += NTHREADS) {
        int row = i / (DHEAD / 4);
        int c4  = (i % (DHEAD / 4)) * 4;
        float4 val = *(const float4*)(qb + row * DHEAD + c4);
        Qs[(c4 + 0) * BM + row] = val.x * scale;
        Qs[(c4 + 1) * BM + row] = val.y * scale;
        Qs[(c4 + 2) * BM + row] = val.z * scale;
        Qs[(c4 + 3) * BM + row] = val.w * scale;
    }

    float acc[4][8];
    #pragma unroll
    for (int i = 0; i < 4; i++)
        #pragma unroll
        for (int j = 0; j < 8; j++) acc[i][j] = 0.0f;

    float m_i[4], l_i[4];
    #pragma unroll
    for (int i = 0; i < 4; i++) { m_i[i] = -3.0e38f; l_i[i] = 0.0f; }

    const int vl = vlen[b];
    const int ntiles = (vl + BN - 1) / BN;   // tiles fully past vl contribute 0 -> skip
    const float* kb = kg + (long)b * Klen * DHEAD;
    const float* vb = vg + (long)b * Klen * DHEAD;

    for (int t = 0; t < ntiles; t++) {
        const int kbase = t * BN;

        __syncthreads();   // previous PV done reading Vs/Ps
        // ---- Load K tile transposed + V tile row-major ----
        for (int i = tid; i < BN * (DHEAD / 4); i += NTHREADS) {
            int row = i / (DHEAD / 4);
            int c4  = (i % (DHEAD / 4)) * 4;
            float4 kval = *(const float4*)(kb + (long)(kbase + row) * DHEAD + c4);
            Ks[(c4 + 0) * BN + row] = kval.x;
            Ks[(c4 + 1) * BN + row] = kval.y;
            Ks[(c4 + 2) * BN + row] = kval.z;
            Ks[(c4 + 3) * BN + row] = kval.w;
            float4 vval = *(const float4*)(vb + (long)(kbase + row) * DHEAD + c4);
            *(float4*)(Vs + row * DHEAD + c4) = vval;
        }
        __syncthreads();

        // ---- S = (Q*scale) @ K^T : each thread 4x4 ----
        float s[4][4];
        #pragma unroll
        for (int i = 0; i < 4; i++)
            #pragma unroll
            for (int j = 0; j < 4; j++) s[i][j] = 0.0f;

        #pragma unroll 4
        for (int d = 0; d < DHEAD; d++) {
            float4 qa = *(const float4*)(Qs + d * BM + 4 * ty);
            float4 kv = *(const float4*)(Ks + d * BN + 4 * tx);
            const float qr[4] = {qa.x, qa.y, qa.z, qa.w};
            const float kr[4] = {kv.x, kv.y, kv.z, kv.w};
            #pragma unroll
            for (int i = 0; i < 4; i++)
                #pragma unroll
                for (int j = 0; j < 4; j++)
                    s[i][j] = fmaf(qr[i], kr[j], s[i][j]);
        }

        // ---- mask columns >= valid_length ----
        #pragma unroll
        for (int j = 0; j < 4; j++) {
            if (kbase + 4 * tx + j >= vl) {
                #pragma unroll
                for (int i = 0; i < 4; i++) s[i][j] = -3.0e38f;
            }
        }

        // ---- online softmax (rows live in 16-lane groups) ----
        float mnew[4], alpha[4], rsum[4];
        #pragma unroll
        for (int i = 0; i < 4; i++) {
            float tmax = fmaxf(fmaxf(s[i][0], s[i][1]), fmaxf(s[i][2], s[i][3]));
            #pragma unroll
            for (int off = 1; off < 16; off <<= 1)
                tmax = fmaxf(tmax, __shfl_xor_sync(0xffffffffu, tmax, off));
            mnew[i]  = fmaxf(m_i[i], tmax);
            alpha[i] = __expf(m_i[i] - mnew[i]);
            m_i[i]   = mnew[i];
        }
        #pragma unroll
        for (int i = 0; i < 4; i++) {
            float rs = 0.0f;
            #pragma unroll
            for (int j = 0; j < 4; j++) {
                s[i][j] = __expf(s[i][j] - mnew[i]);   // s becomes P
                rs += s[i][j];
            }
            #pragma unroll
            for (int off = 1; off < 16; off <<= 1)
                rs += __shfl_xor_sync(0xffffffffu, rs, off);
            l_i[i] = l_i[i] * alpha[i] + rs;
            #pragma unroll
            for (int j = 0; j < 8; j++) acc[i][j] *= alpha[i];
        }

        // ---- store P transposed: Ps[k][q] ----
        #pragma unroll
        for (int j = 0; j < 4; j++) {
            float4 pc = make_float4(s[0][j], s[1][j], s[2][j], s[3][j]);
            *(float4*)(Ps + (4 * tx + j) * PS_STRIDE + 4 * ty) = pc;
        }
        __syncthreads();

        // ---- O += P @ V : each thread 4q x 8d ----
        #pragma unroll 2
        for (int kk = 0; kk < BN; kk++) {
            float4 pr = *(const float4*)(Ps + kk * PS_STRIDE + 4 * ty);
            float4 va = *(const float4*)(Vs + kk * DHEAD + 4 * tx);
            float4 vbv = *(const float4*)(Vs + kk * DHEAD + 64 + 4 * tx);
            const float p[4] = {pr.x, pr.y, pr.z, pr.w};
            #pragma unroll
            for (int i = 0; i < 4; i++) {
                acc[i][0] = fmaf(p[i], va.x,  acc[i][0]);
                acc[i][1] = fmaf(p[i], va.y,  acc[i][1]);
                acc[i][2] = fmaf(p[i], va.z,  acc[i][2]);
                acc[i][3] = fmaf(p[i], va.w,  acc[i][3]);
                acc[i][4] = fmaf(p[i], vbv.x, acc[i][4]);
                acc[i][5] = fmaf(p[i], vbv.y, acc[i][5]);
                acc[i][6] = fmaf(p[i], vbv.z, acc[i][6]);
                acc[i][7] = fmaf(p[i], vbv.w, acc[i][7]);
            }
        }
    }

    // ---- epilogue: O /= l, write ----
    float* ob = outg + ((long)b * Qlen + q0) * DHEAD;
    #pragma unroll
    for (int i = 0; i < 4; i++) {
        float inv = 1.0f / l_i[i];
        int row = 4 * ty + i;
        float4 o0 = make_float4(acc[i][0] * inv, acc[i][1] * inv,
                                acc[i][2] * inv, acc[i][3] * inv);
        float4 o1 = make_float4(acc[i][4] * inv, acc[i][5] * inv,
                                acc[i][6] * inv, acc[i][7] * inv);
        *(float4*)(ob + row * DHEAD + 4 * tx)      = o0;
        *(float4*)(ob + row * DHEAD + 64 + 4 * tx) = o1;
    }
}

extern "C" void kernel_launch(void* const* d_in, const int* in_sizes, int n_in,
                              void* d_out, int out_size)
{
    const float* q  = (const float*)d_in[0];
    const float* k  = (const float*)d_in[1];
    const float* v  = (const float*)d_in[2];
    const int*   vl = (const int*)d_in[3];

    const int B    = in_sizes[3];
    const int Qlen = in_sizes[0] / (B * DHEAD);
    const int Klen = in_sizes[1] / (B * DHEAD);

    size_t smem = (size_t)(DHEAD * BM + DHEAD * BN + BN * DHEAD + BN * PS_STRIDE) * sizeof(float);
    cudaFuncSetAttribute(attn_fp32_kernel,
                         cudaFuncAttributeMaxDynamicSharedMemorySize, (int)smem);

    dim3 grid(Qlen / BM, B);
    attn_fp32_kernel<<<grid, NTHREADS, smem>>>(q, k, v, vl, (float*)d_out, Qlen, Klen);
}

// round 2
// speedup vs baseline: 2.0068x; 2.0068x over previous
#include <cuda_runtime.h>
#include <cstdint>
#include <math.h>

#define DHEAD 128
#define BM 128            // q rows per CTA (8 warps x 16)
#define BN 64             // keys per tile
#define NTH 256
#define KSTR 132          // K smem row stride (floats): (4g+c) bank pattern -> conflict-free
#define VSTR 136          // V smem row stride: 136%32==8 -> (8c+g) conflict-free
#define PSTR 68           // P smem row stride: 68%32==4 -> (4g+c) conflict-free

// smem float offsets
#define KB0 0
#define KB1 (BN*KSTR)                 // 8448
#define VB0 (2*BN*KSTR)               // 16896
#define VB1 (2*BN*KSTR + BN*VSTR)     // 25600
#define PB  (2*BN*KSTR + 2*BN*VSTR)   // 34304
#define SMEM_FLOATS (PB + 8*16*PSTR)  // 43008 -> 172032 B

__device__ __forceinline__ uint32_t f2tf(float x) {
    uint32_t r; asm("cvt.rna.tf32.f32 %0, %1;" : "=r"(r) : "f"(x)); return r;
}
__device__ __forceinline__ void tfsplit(float x, uint32_t& h, uint32_t& l) {
    h = f2tf(x);
    l = f2tf(x - __uint_as_float(h));
}
__device__ __forceinline__ void mma_tf32(float c[4],
    uint32_t a0, uint32_t a1, uint32_t a2, uint32_t a3,
    uint32_t b0, uint32_t b1)
{
    asm volatile("mma.sync.aligned.m16n8k8.row.col.f32.tf32.tf32.f32 "
        "{%0,%1,%2,%3}, {%4,%5,%6,%7}, {%8,%9}, {%0,%1,%2,%3};"
        : "+f"(c[0]), "+f"(c[1]), "+f"(c[2]), "+f"(c[3])
        : "r"(a0), "r"(a1), "r"(a2), "r"(a3), "r"(b0), "r"(b1));
}
__device__ __forceinline__ void cpasync16(float* dst, const float* src) {
    uint32_t d = (uint32_t)__cvta_generic_to_shared(dst);
    asm volatile("cp.async.cg.shared.global [%0], [%1], 16;" :: "r"(d), "l"(src));
}

__global__ __launch_bounds__(NTH, 1)
void attn_tf32_kernel(const float* __restrict__ qg,
                      const float* __restrict__ kg,
                      const float* __restrict__ vg,
                      const int*   __restrict__ vlen,
                      float*       __restrict__ outg,
                      int Qlen, int Klen)
{
    extern __shared__ float sm[];
    const int b  = blockIdx.y;
    const int q0 = blockIdx.x * BM;
    const int tid  = threadIdx.x;
    const int w    = tid >> 5;
    const int lane = tid & 31;
    const int g    = lane >> 2;    // group id (row within 8)
    const int c    = lane & 3;     // thread-in-group

    const int vl = vlen[b];
    const int ntiles = (vl + BN - 1) / BN;

    const float* kb = kg + (long)b * Klen * DHEAD;
    const float* vb = vg + (long)b * Klen * DHEAD;

    // ---- Q fragments in registers (pre-scaled). qv[r][s8][h]: r=0 row g, r=1 row g+8.
    const float scale = 0.08838834764831845f;  // 1/sqrt(128)
    const int r0 = q0 + 16 * w + g;
    const int r1 = r0 + 8;
    float qv[2][16][2];
    {
        const float* qr0 = qg + ((long)b * Qlen + r0) * DHEAD;
        const float* qr1 = qg + ((long)b * Qlen + r1) * DHEAD;
        #pragma unroll
        for (int s8 = 0; s8 < 16; s8++) {
            qv[0][s8][0] = qr0[8 * s8 + c]     * scale;
            qv[0][s8][1] = qr0[8 * s8 + c + 4] * scale;
            qv[1][s8][0] = qr1[8 * s8 + c]     * scale;
            qv[1][s8][1] = qr1[8 * s8 + c + 4] * scale;
        }
    }

    // ---- prefetch tile 0
    {
        float* Ks = sm + KB0;
        float* Vs = sm + VB0;
        #pragma unroll
        for (int it = 0; it < 8; it++) {
            int idx = tid + it * NTH;           // 0..2047
            int row = idx >> 5;
            int c4  = (idx & 31) << 2;
            cpasync16(Ks + row * KSTR + c4, kb + (long)row * DHEAD + c4);
            cpasync16(Vs + row * VSTR + c4, vb + (long)row * DHEAD + c4);
        }
        asm volatile("cp.async.commit_group;");
    }

    float o[16][4];
    #pragma unroll
    for (int j = 0; j < 16; j++)
        #pragma unroll
        for (int i = 0; i < 4; i++) o[j][i] = 0.0f;
    float m0 = -3.0e38f, m1 = -3.0e38f, l0 = 0.0f, l1 = 0.0f;

    float* Pw = sm + PB + w * 16 * PSTR;

    for (int t = 0; t < ntiles; t++) {
        asm volatile("cp.async.wait_group 0;");
        __syncthreads();

        // prefetch next tile into the other buffer
        if (t + 1 < ntiles) {
            const float* kn = kb + (long)(t + 1) * BN * DHEAD;
            const float* vn = vb + (long)(t + 1) * BN * DHEAD;
            float* Ks = sm + (((t + 1) & 1) ? KB1 : KB0);
            float* Vs = sm + (((t + 1) & 1) ? VB1 : VB0);
            #pragma unroll
            for (int it = 0; it < 8; it++) {
                int idx = tid + it * NTH;
                int row = idx >> 5;
                int c4  = (idx & 31) << 2;
                cpasync16(Ks + row * KSTR + c4, kn + (long)row * DHEAD + c4);
                cpasync16(Vs + row * VSTR + c4, vn + (long)row * DHEAD + c4);
            }
            asm volatile("cp.async.commit_group;");
        }

        const float* Ks = sm + ((t & 1) ? KB1 : KB0);
        const float* Vs = sm + ((t & 1) ? VB1 : VB0);

        // ---- S = Q @ K^T (3xTF32), warp rows [16w,16w+16), keys [0,64)
        float s[8][4];
        #pragma unroll
        for (int j = 0; j < 8; j++)
            #pragma unroll
            for (int i = 0; i < 4; i++) s[j][i] = 0.0f;

        #pragma unroll
        for (int s8 = 0; s8 < 16; s8++) {
            uint32_t ah[4], al[4];
            tfsplit(qv[0][s8][0], ah[0], al[0]);
            tfsplit(qv[1][s8][0], ah[1], al[1]);
            tfsplit(qv[0][s8][1], ah[2], al[2]);
            tfsplit(qv[1][s8][1], ah[3], al[3]);
            #pragma unroll
            for (int j = 0; j < 8; j++) {
                float bf0 = Ks[(8 * j + g) * KSTR + 8 * s8 + c];
                float bf1 = Ks[(8 * j + g) * KSTR + 8 * s8 + c + 4];
                uint32_t bh0, bl0, bh1, bl1;
                tfsplit(bf0, bh0, bl0);
                tfsplit(bf1, bh1, bl1);
                mma_tf32(s[j], ah[0], ah[1], ah[2], ah[3], bh0, bh1);
                mma_tf32(s[j], al[0], al[1], al[2], al[3], bh0, bh1);
                mma_tf32(s[j], ah[0], ah[1], ah[2], ah[3], bl0, bl1);
            }
        }

        // ---- mask invalid keys
        const int kbase = t * BN;
        #pragma unroll
        for (int j = 0; j < 8; j++) {
            int col = kbase + 8 * j + 2 * c;
            if (col     >= vl) { s[j][0] = -3.0e38f; s[j][2] = -3.0e38f; }
            if (col + 1 >= vl) { s[j][1] = -3.0e38f; s[j][3] = -3.0e38f; }
        }

        // ---- online softmax (rows g and g+8; reduce over c via xor 1,2)
        float mx0 = -3.0e38f, mx1 = -3.0e38f;
        #pragma unroll
        for (int j = 0; j < 8; j++) {
            mx0 = fmaxf(mx0, fmaxf(s[j][0], s[j][1]));
            mx1 = fmaxf(mx1, fmaxf(s[j][2], s[j][3]));
        }
        mx0 = fmaxf(mx0, __shfl_xor_sync(0xffffffffu, mx0, 1));
        mx0 = fmaxf(mx0, __shfl_xor_sync(0xffffffffu, mx0, 2));
        mx1 = fmaxf(mx1, __shfl_xor_sync(0xffffffffu, mx1, 1));
        mx1 = fmaxf(mx1, __shfl_xor_sync(0xffffffffu, mx1, 2));

        float mn0 = fmaxf(m0, mx0), mn1 = fmaxf(m1, mx1);
        float a0s = __expf(m0 - mn0), a1s = __expf(m1 - mn1);
        m0 = mn0; m1 = mn1;

        float rs0 = 0.0f, rs1 = 0.0f;
        #pragma unroll
        for (int j = 0; j < 8; j++) {
            s[j][0] = __expf(s[j][0] - mn0); rs0 += s[j][0];
            s[j][1] = __expf(s[j][1] - mn0); rs0 += s[j][1];
            s[j][2] = __expf(s[j][2] - mn1); rs1 += s[j][2];
            s[j][3] = __expf(s[j][3] - mn1); rs1 += s[j][3];
        }
        rs0 += __shfl_xor_sync(0xffffffffu, rs0, 1);
        rs0 += __shfl_xor_sync(0xffffffffu, rs0, 2);
        rs1 += __shfl_xor_sync(0xffffffffu, rs1, 1);
        rs1 += __shfl_xor_sync(0xffffffffu, rs1, 2);
        l0 = l0 * a0s + rs0;
        l1 = l1 * a1s + rs1;

        #pragma unroll
        for (int j = 0; j < 16; j++) {
            o[j][0] *= a0s; o[j][1] *= a0s;
            o[j][2] *= a1s; o[j][3] *= a1s;
        }

        // ---- spill P to per-warp smem
        #pragma unroll
        for (int j = 0; j < 8; j++) {
            *(float2*)(Pw + g       * PSTR + 8 * j + 2 * c) = make_float2(s[j][0], s[j][1]);
            *(float2*)(Pw + (g + 8) * PSTR + 8 * j + 2 * c) = make_float2(s[j][2], s[j][3]);
        }
        __syncwarp();

        // ---- O += P @ V (3xTF32), k = 64 keys, n = 128 d
        #pragma unroll 2
        for (int s8 = 0; s8 < 8; s8++) {
            float pf0 = Pw[g       * PSTR + 8 * s8 + c];
            float pf1 = Pw[g       * PSTR + 8 * s8 + c + 4];
            float pf2 = Pw[(g + 8) * PSTR + 8 * s8 + c];
            float pf3 = Pw[(g + 8) * PSTR + 8 * s8 + c + 4];
            uint32_t ah[4], al[4];
            tfsplit(pf0, ah[0], al[0]);
            tfsplit(pf2, ah[1], al[1]);
            tfsplit(pf1, ah[2], al[2]);
            tfsplit(pf3, ah[3], al[3]);
            #pragma unroll
            for (int j = 0; j < 16; j++) {
                float bf0 = Vs[(8 * s8 + c)     * VSTR + 8 * j + g];
                float bf1 = Vs[(8 * s8 + c + 4) * VSTR + 8 * j + g];
                uint32_t bh0, bl0, bh1, bl1;
                tfsplit(bf0, bh0, bl0);
                tfsplit(bf1, bh1, bl1);
                mma_tf32(o[j], ah[0], ah[1], ah[2], ah[3], bh0, bh1);
                mma_tf32(o[j], al[0], al[1], al[2], al[3], bh0, bh1);
                mma_tf32(o[j], ah[0], ah[1], ah[2], ah[3], bl0, bl1);
            }
        }
    }

    // ---- epilogue
    const float i0 = 1.0f / l0;
    const float i1 = 1.0f / l1;
    float* or0 = outg + ((long)b * Qlen + r0) * DHEAD;
    float* or1 = outg + ((long)b * Qlen + r1) * DHEAD;
    #pragma unroll
    for (int j = 0; j < 16; j++) {
        *(float2*)(or0 + 8 * j + 2 * c) = make_float2(o[j][0] * i0, o[j][1] * i0);
        *(float2*)(or1 + 8 * j + 2 * c) = make_float2(o[j][2] * i1, o[j][3] * i1);
    }
}

extern "C" void kernel_launch(void* const* d_in, const int* in_sizes, int n_in,
                              void* d_out, int out_size)
{
    const float* q  = (const float*)d_in[0];
    const float* k  = (const float*)d_in[1];
    const float* v  = (const float*)d_in[2];
    const int*   vl = (const int*)d_in[3];

    const int B    = in_sizes[3];
    const int Qlen = in_sizes[0] / (B * DHEAD);
    const int Klen = in_sizes[1] / (B * DHEAD);

    size_t smem = (size_t)SMEM_FLOATS * sizeof(float);
    cudaFuncSetAttribute(attn_tf32_kernel,
                         cudaFuncAttributeMaxDynamicSharedMemorySize, (int)smem);

    dim3 grid(Qlen / BM, B);
    attn_tf32_kernel<<<grid, NTH, smem>>>(q, k, v, vl, (float*)d_out, Qlen, Klen);
}

// round 3
// speedup vs baseline: 3.7971x; 1.8921x over previous
#include <cuda_runtime.h>
#include <cuda_bf16.h>
#include <cstdint>
#include <math.h>

#define DHEAD 128
#define BM 128            // q rows per CTA (8 warps x 16)
#define BN 64             // keys per tile
#define NTH 256

// staging strides (floats): 132 -> conflict-free convert reads, 16B-aligned rows
#define KSTG 132
// packed bf16 strides (32-bit words): ≡4 mod 32 -> conflict-free fragment LDS
#define KPSTR 68          // Khi/Klo: [key][pair(d/2)]   64 pairs + 4 pad
#define VPSTR 36          // Vhi/Vlo: [d][keypair]       32 pairs + 4 pad

// smem float offsets
#define OFF_KST 0
#define OFF_VST (BN*KSTG)                    // 8448
#define OFF_KHI (2*BN*KSTG)                  // 16896
#define OFF_KLO (OFF_KHI + BN*KPSTR)         // 21248
#define OFF_VHI (OFF_KLO + BN*KPSTR)         // 25600
#define OFF_VLO (OFF_VHI + DHEAD*VPSTR)      // 30208
#define SMEM_FLOATS (OFF_VLO + DHEAD*VPSTR)  // 34816 -> 139264 B

__device__ __forceinline__ uint32_t packbf2(float x, float y) {
    __nv_bfloat162 t = __floats2bfloat162_rn(x, y);
    return *(uint32_t*)&t;
}
__device__ __forceinline__ void hilo(float x, float& h, float& l) {
    __nv_bfloat16 hb = __float2bfloat16_rn(x);
    h = __bfloat162float(hb);
    l = x - h;
}
__device__ __forceinline__ void mma_bf16(float c[4],
    uint32_t a0, uint32_t a1, uint32_t a2, uint32_t a3,
    uint32_t b0, uint32_t b1)
{
    asm volatile("mma.sync.aligned.m16n8k16.row.col.f32.bf16.bf16.f32 "
        "{%0,%1,%2,%3}, {%4,%5,%6,%7}, {%8,%9}, {%0,%1,%2,%3};"
        : "+f"(c[0]), "+f"(c[1]), "+f"(c[2]), "+f"(c[3])
        : "r"(a0), "r"(a1), "r"(a2), "r"(a3), "r"(b0), "r"(b1));
}
__device__ __forceinline__ void cpasync16(float* dst, const float* src) {
    uint32_t d = (uint32_t)__cvta_generic_to_shared(dst);
    asm volatile("cp.async.cg.shared.global [%0], [%1], 16;" :: "r"(d), "l"(src));
}

__global__ __launch_bounds__(NTH, 1)
void attn_bf16x3_kernel(const float* __restrict__ qg,
                        const float* __restrict__ kg,
                        const float* __restrict__ vg,
                        const int*   __restrict__ vlen,
                        float*       __restrict__ outg,
                        int Qlen, int Klen)
{
    extern __shared__ float sm[];
    float*    Kst = sm + OFF_KST;
    float*    Vst = sm + OFF_VST;
    uint32_t* Khi = (uint32_t*)(sm + OFF_KHI);
    uint32_t* Klo = (uint32_t*)(sm + OFF_KLO);
    uint32_t* Vhi = (uint32_t*)(sm + OFF_VHI);
    uint32_t* Vlo = (uint32_t*)(sm + OFF_VLO);

    const int b  = blockIdx.y;
    const int q0 = blockIdx.x * BM;
    const int tid  = threadIdx.x;
    const int w    = tid >> 5;
    const int lane = tid & 31;
    const int g    = lane >> 2;
    const int c    = lane & 3;

    const int vl = vlen[b];
    const int ntiles = (vl + BN - 1) / BN;

    const float* kb = kg + (long)b * Klen * DHEAD;
    const float* vb = vg + (long)b * Klen * DHEAD;

    // ---- Q fragments: hi/lo bf16-packed, pre-scaled. 8 k16-blocks x 4 regs each.
    const float scale = 0.08838834764831845f;  // 1/sqrt(128)
    const int r0 = q0 + 16 * w + g;
    const int r1 = r0 + 8;
    uint32_t qh[8][4], ql[8][4];
    {
        const float* qr0 = qg + ((long)b * Qlen + r0) * DHEAD;
        const float* qr1 = qg + ((long)b * Qlen + r1) * DHEAD;
        #pragma unroll
        for (int kbk = 0; kbk < 8; kbk++) {
            int base = 16 * kbk + 2 * c;
            float h0,l0,h1,l1;
            hilo(qr0[base]     * scale, h0, l0);
            hilo(qr0[base + 1] * scale, h1, l1);
            qh[kbk][0] = packbf2(h0, h1); ql[kbk][0] = packbf2(l0, l1);
            hilo(qr1[base]     * scale, h0, l0);
            hilo(qr1[base + 1] * scale, h1, l1);
            qh[kbk][1] = packbf2(h0, h1); ql[kbk][1] = packbf2(l0, l1);
            hilo(qr0[base + 8] * scale, h0, l0);
            hilo(qr0[base + 9] * scale, h1, l1);
            qh[kbk][2] = packbf2(h0, h1); ql[kbk][2] = packbf2(l0, l1);
            hilo(qr1[base + 8] * scale, h0, l0);
            hilo(qr1[base + 9] * scale, h1, l1);
            qh[kbk][3] = packbf2(h0, h1); ql[kbk][3] = packbf2(l0, l1);
        }
    }

    // ---- prefetch tile 0 into staging
    {
        #pragma unroll
        for (int it = 0; it < 8; it++) {
            int idx = tid + it * NTH;
            int row = idx >> 5;
            int c4  = (idx & 31) << 2;
            cpasync16(Kst + row * KSTG + c4, kb + (long)row * DHEAD + c4);
            cpasync16(Vst + row * KSTG + c4, vb + (long)row * DHEAD + c4);
        }
        asm volatile("cp.async.commit_group;");
    }

    float o[16][4];
    #pragma unroll
    for (int j = 0; j < 16; j++)
        #pragma unroll
        for (int i = 0; i < 4; i++) o[j][i] = 0.0f;
    float m0 = -3.0e38f, m1 = -3.0e38f, l0s = 0.0f, l1s = 0.0f;

    for (int t = 0; t < ntiles; t++) {
        asm volatile("cp.async.wait_group 0;");
        __syncthreads();

        // ---- convert pass: staging fp32 -> packed bf16 hi/lo
        {
            // K: thread -> (key = tid>>2, quarter = tid&3), 8 float4 each
            int key = tid >> 2;
            int q4  = tid & 3;
            #pragma unroll
            for (int i = 0; i < 8; i++) {
                int d4 = q4 * 8 + i;
                float4 v = *(const float4*)(Kst + key * KSTG + d4 * 4);
                float h0,lo0,h1,lo1,h2,lo2,h3,lo3;
                hilo(v.x, h0, lo0); hilo(v.y, h1, lo1);
                hilo(v.z, h2, lo2); hilo(v.w, h3, lo3);
                Khi[key * KPSTR + 2 * d4]     = packbf2(h0, h1);
                Khi[key * KPSTR + 2 * d4 + 1] = packbf2(h2, h3);
                Klo[key * KPSTR + 2 * d4]     = packbf2(lo0, lo1);
                Klo[key * KPSTR + 2 * d4 + 1] = packbf2(lo2, lo3);
            }
            // V: thread -> (keypair = tid&31, dgroup = tid>>5), 4 float4-pairs
            int kp   = tid & 31;
            int dgrp = tid >> 5;
            #pragma unroll
            for (int i = 0; i < 4; i++) {
                int d4 = dgrp * 4 + i;
                float4 va = *(const float4*)(Vst + (2 * kp)     * KSTG + d4 * 4);
                float4 vbv= *(const float4*)(Vst + (2 * kp + 1) * KSTG + d4 * 4);
                const float xa[4] = {va.x, va.y, va.z, va.w};
                const float xb[4] = {vbv.x, vbv.y, vbv.z, vbv.w};
                #pragma unroll
                for (int j = 0; j < 4; j++) {
                    float ha,la,hb,lb;
                    hilo(xa[j], ha, la);
                    hilo(xb[j], hb, lb);
                    int d = d4 * 4 + j;
                    Vhi[d * VPSTR + kp] = packbf2(ha, hb);
                    Vlo[d * VPSTR + kp] = packbf2(la, lb);
                }
            }
        }
        __syncthreads();

        // ---- prefetch next tile into staging (now free)
        if (t + 1 < ntiles) {
            const float* kn = kb + (long)(t + 1) * BN * DHEAD;
            const float* vn = vb + (long)(t + 1) * BN * DHEAD;
            #pragma unroll
            for (int it = 0; it < 8; it++) {
                int idx = tid + it * NTH;
                int row = idx >> 5;
                int c4  = (idx & 31) << 2;
                cpasync16(Kst + row * KSTG + c4, kn + (long)row * DHEAD + c4);
                cpasync16(Vst + row * KSTG + c4, vn + (long)row * DHEAD + c4);
            }
            asm volatile("cp.async.commit_group;");
        }

        // ---- S = Q @ K^T : 3x bf16 m16n8k16
        float s[8][4];
        #pragma unroll
        for (int j = 0; j < 8; j++)
            #pragma unroll
            for (int i = 0; i < 4; i++) s[j][i] = 0.0f;

        #pragma unroll
        for (int kbk = 0; kbk < 8; kbk++) {
            #pragma unroll
            for (int j = 0; j < 8; j++) {
                int rowb = (8 * j + g) * KPSTR + 8 * kbk + c;
                uint32_t bh0 = Khi[rowb];
                uint32_t bh1 = Khi[rowb + 4];
                uint32_t bl0 = Klo[rowb];
                uint32_t bl1 = Klo[rowb + 4];
                mma_bf16(s[j], qh[kbk][0], qh[kbk][1], qh[kbk][2], qh[kbk][3], bh0, bh1);
                mma_bf16(s[j], ql[kbk][0], ql[kbk][1], ql[kbk][2], ql[kbk][3], bh0, bh1);
                mma_bf16(s[j], qh[kbk][0], qh[kbk][1], qh[kbk][2], qh[kbk][3], bl0, bl1);
            }
        }

        // ---- mask invalid keys
        const int kbase = t * BN;
        #pragma unroll
        for (int j = 0; j < 8; j++) {
            int col = kbase + 8 * j + 2 * c;
            if (col     >= vl) { s[j][0] = -3.0e38f; s[j][2] = -3.0e38f; }
            if (col + 1 >= vl) { s[j][1] = -3.0e38f; s[j][3] = -3.0e38f; }
        }

        // ---- online softmax
        float mx0 = -3.0e38f, mx1 = -3.0e38f;
        #pragma unroll
        for (int j = 0; j < 8; j++) {
            mx0 = fmaxf(mx0, fmaxf(s[j][0], s[j][1]));
            mx1 = fmaxf(mx1, fmaxf(s[j][2], s[j][3]));
        }
        mx0 = fmaxf(mx0, __shfl_xor_sync(0xffffffffu, mx0, 1));
        mx0 = fmaxf(mx0, __shfl_xor_sync(0xffffffffu, mx0, 2));
        mx1 = fmaxf(mx1, __shfl_xor_sync(0xffffffffu, mx1, 1));
        mx1 = fmaxf(mx1, __shfl_xor_sync(0xffffffffu, mx1, 2));

        float mn0 = fmaxf(m0, mx0), mn1 = fmaxf(m1, mx1);
        float a0s = __expf(m0 - mn0), a1s = __expf(m1 - mn1);
        m0 = mn0; m1 = mn1;

        float rs0 = 0.0f, rs1 = 0.0f;
        #pragma unroll
        for (int j = 0; j < 8; j++) {
            s[j][0] = __expf(s[j][0] - mn0); rs0 += s[j][0];
            s[j][1] = __expf(s[j][1] - mn0); rs0 += s[j][1];
            s[j][2] = __expf(s[j][2] - mn1); rs1 += s[j][2];
            s[j][3] = __expf(s[j][3] - mn1); rs1 += s[j][3];
        }
        rs0 += __shfl_xor_sync(0xffffffffu, rs0, 1);
        rs0 += __shfl_xor_sync(0xffffffffu, rs0, 2);
        rs1 += __shfl_xor_sync(0xffffffffu, rs1, 1);
        rs1 += __shfl_xor_sync(0xffffffffu, rs1, 2);
        l0s = l0s * a0s + rs0;
        l1s = l1s * a1s + rs1;

        #pragma unroll
        for (int j = 0; j < 16; j++) {
            o[j][0] *= a0s; o[j][1] *= a0s;
            o[j][2] *= a1s; o[j][3] *= a1s;
        }

        // ---- O += P @ V : P stays in registers (fragment layouts match)
        #pragma unroll
        for (int kbk = 0; kbk < 4; kbk++) {
            float h00,lo00,h01,lo01,h02,lo02,h03,lo03;
            float h10,lo10,h11,lo11,h12,lo12,h13,lo13;
            hilo(s[2*kbk][0], h00, lo00); hilo(s[2*kbk][1], h01, lo01);
            hilo(s[2*kbk][2], h02, lo02); hilo(s[2*kbk][3], h03, lo03);
            hilo(s[2*kbk+1][0], h10, lo10); hilo(s[2*kbk+1][1], h11, lo11);
            hilo(s[2*kbk+1][2], h12, lo12); hilo(s[2*kbk+1][3], h13, lo13);
            uint32_t ah0 = packbf2(h00, h01),  ah1 = packbf2(h02, h03);
            uint32_t ah2 = packbf2(h10, h11),  ah3 = packbf2(h12, h13);
            uint32_t al0 = packbf2(lo00, lo01), al1 = packbf2(lo02, lo03);
            uint32_t al2 = packbf2(lo10, lo11), al3 = packbf2(lo12, lo13);
            #pragma unroll
            for (int j = 0; j < 16; j++) {
                int rowb = (8 * j + g) * VPSTR + 8 * kbk + c;
                uint32_t bh0 = Vhi[rowb];
                uint32_t bh1 = Vhi[rowb + 4];
                uint32_t bl0 = Vlo[rowb];
                uint32_t bl1 = Vlo[rowb + 4];
                mma_bf16(o[j], ah0, ah1, ah2, ah3, bh0, bh1);
                mma_bf16(o[j], al0, al1, al2, al3, bh0, bh1);
                mma_bf16(o[j], ah0, ah1, ah2, ah3, bl0, bl1);
            }
        }
    }

    // ---- epilogue
    const float i0 = 1.0f / l0s;
    const float i1 = 1.0f / l1s;
    float* or0 = outg + ((long)b * Qlen + r0) * DHEAD;
    float* or1 = outg + ((long)b * Qlen + r1) * DHEAD;
    #pragma unroll
    for (int j = 0; j < 16; j++) {
        *(float2*)(or0 + 8 * j + 2 * c) = make_float2(o[j][0] * i0, o[j][1] * i0);
        *(float2*)(or1 + 8 * j + 2 * c) = make_float2(o[j][2] * i1, o[j][3] * i1);
    }
}

extern "C" void kernel_launch(void* const* d_in, const int* in_sizes, int n_in,
                              void* d_out, int out_size)
{
    const float* q  = (const float*)d_in[0];
    const float* k  = (const float*)d_in[1];
    const float* v  = (const float*)d_in[2];
    const int*   vl = (const int*)d_in[3];

    const int B    = in_sizes[3];
    const int Qlen = in_sizes[0] / (B * DHEAD);
    const int Klen = in_sizes[1] / (B * DHEAD);

    size_t smem = (size_t)SMEM_FLOATS * sizeof(float);
    cudaFuncSetAttribute(attn_bf16x3_kernel,
                         cudaFuncAttributeMaxDynamicSharedMemorySize, (int)smem);

    dim3 grid(Qlen / BM, B);
    attn_bf16x3_kernel<<<grid, NTH, smem>>>(q, k, v, vl, (float*)d_out, Qlen, Klen);
}